// round 7
// baseline (speedup 1.0000x reference)
#include <cuda_runtime.h>
#include <cstdint>

#define NN 50000
#define NE 800000
constexpr float NEG_SLOPE = 0.2f;

// ---------------- scratch (device globals; no allocation) ----------------
__device__ float g_h  [NN * 256];
__device__ float g_z1 [NN * 256];
__device__ float g_z2 [NN * 32];
__device__ float g_r1 [NN * 256];
__device__ float g_als[NN * 8];
__device__ float g_ald[NN * 8];
__device__ int   g_deg[NN];
__device__ int   g_cnt[NN];
__device__ int   g_off[NN + 1];
__device__ int   g_csr[NE + NN];

// ================= CSR build =================
__global__ void hist_kernel(const int* __restrict__ ei, int* __restrict__ deg) {
    int e = blockIdx.x * blockDim.x + threadIdx.x;
    if (e < NE) atomicAdd(&deg[ei[NE + e]], 1);
}

__global__ void scan_kernel(const int* __restrict__ deg, int* __restrict__ off) {
    __shared__ int wsum[32];
    __shared__ int carry_s;
    int tid = threadIdx.x, lane = tid & 31, wid = tid >> 5;
    if (tid == 0) { carry_s = 0; off[0] = 0; }
    __syncthreads();
    for (int base = 0; base < NN; base += 1024) {
        int i = base + tid;
        int v = (i < NN) ? deg[i] + 1 : 0;
        int x = v;
#pragma unroll
        for (int o = 1; o < 32; o <<= 1) {
            int t = __shfl_up_sync(0xffffffffu, x, o);
            if (lane >= o) x += t;
        }
        if (lane == 31) wsum[wid] = x;
        __syncthreads();
        if (wid == 0) {
            int y = wsum[lane];
#pragma unroll
            for (int o = 1; o < 32; o <<= 1) {
                int t = __shfl_up_sync(0xffffffffu, y, o);
                if (lane >= o) y += t;
            }
            wsum[lane] = y;
        }
        __syncthreads();
        int incl = x + (wid > 0 ? wsum[wid - 1] : 0) + carry_s;
        if (i < NN) off[i + 1] = incl;
        __syncthreads();
        if (tid == 1023) carry_s = incl;
        __syncthreads();
    }
}

__global__ void scatter_kernel(const int* __restrict__ ei, const int* __restrict__ off,
                               int* __restrict__ cnt, int* __restrict__ csr) {
    int e = blockIdx.x * blockDim.x + threadIdx.x;
    if (e < NE) {
        int d = ei[NE + e];
        int pos = off[d] + atomicAdd(&cnt[d], 1);
        csr[pos] = ei[e];
    } else if (e < NE + NN) {
        int n = e - NE;
        csr[off[n + 1] - 1] = n;  // self loop in last slot
    }
}

// ================= double-buffered SGEMM: C[N,M] = A[N,K] @ B[K,M] ==========
template <int BM, int BN, int BK, int TM, int TN>
__global__ void __launch_bounds__((BM / TM) * (BN / TN))
sgemm_db_kernel(int N, int K, int M,
                const float* __restrict__ A, const float* __restrict__ B,
                float* __restrict__ C) {
    constexpr int TX = BN / TN;
    constexpr int TY = BM / TM;
    constexpr int THREADS = TX * TY;
    constexpr int APF = BM * BK / (THREADS * 4);
    constexpr int BPF = BK * BN / (THREADS * 4);

    __shared__ float As[BK][BM];
    __shared__ float Bs[BK][BN];

    const int tid = threadIdx.x;
    const int tx = tid % TX;
    const int ty = tid / TX;
    const int row0 = blockIdx.x * BM;
    const int col0 = blockIdx.y * BN;

    float4 pa[APF], pb[BPF];
    float acc[TM][TN];
#pragma unroll
    for (int m = 0; m < TM; m++)
#pragma unroll
        for (int n = 0; n < TN; n++) acc[m][n] = 0.f;

    auto load_tiles = [&](int k0) {
#pragma unroll
        for (int p = 0; p < APF; p++) {
            int i = (tid + p * THREADS) * 4;
            int r = i / BK, kk = i % BK;
            float4 v = make_float4(0.f, 0.f, 0.f, 0.f);
            if (row0 + r < N)
                v = *(const float4*)&A[(size_t)(row0 + r) * K + k0 + kk];
            pa[p] = v;
        }
#pragma unroll
        for (int p = 0; p < BPF; p++) {
            int i = (tid + p * THREADS) * 4;
            int kk = i / BN, c = i % BN;
            pb[p] = *(const float4*)&B[(size_t)(k0 + kk) * M + col0 + c];
        }
    };
    auto store_tiles = [&]() {
#pragma unroll
        for (int p = 0; p < APF; p++) {
            int i = (tid + p * THREADS) * 4;
            int r = i / BK, kk = i % BK;
            As[kk + 0][r] = pa[p].x;
            As[kk + 1][r] = pa[p].y;
            As[kk + 2][r] = pa[p].z;
            As[kk + 3][r] = pa[p].w;
        }
#pragma unroll
        for (int p = 0; p < BPF; p++) {
            int i = (tid + p * THREADS) * 4;
            int kk = i / BN, c = i % BN;
            *(float4*)&Bs[kk][c] = pb[p];
        }
    };

    load_tiles(0);
    store_tiles();
    __syncthreads();

    int k0 = 0;
    while (true) {
        int kn = k0 + BK;
        if (kn < K) load_tiles(kn);   // prefetch next while computing current

#pragma unroll
        for (int kk = 0; kk < BK; kk++) {
            float ra[TM], rb[TN];
#pragma unroll
            for (int m = 0; m < TM; m += 4)
                *(float4*)&ra[m] = *(const float4*)&As[kk][ty * TM + m];
#pragma unroll
            for (int n = 0; n < TN; n += 4)
                *(float4*)&rb[n] = *(const float4*)&Bs[kk][tx * TN + n];
#pragma unroll
            for (int m = 0; m < TM; m++)
#pragma unroll
                for (int n = 0; n < TN; n++) acc[m][n] += ra[m] * rb[n];
        }

        if (kn >= K) break;
        __syncthreads();
        store_tiles();
        __syncthreads();
        k0 = kn;
    }

#pragma unroll
    for (int m = 0; m < TM; m++) {
        int r = row0 + ty * TM + m;
        if (r < N) {
#pragma unroll
            for (int n = 0; n < TN; n += 4) {
                float4 v = make_float4(acc[m][n], acc[m][n + 1], acc[m][n + 2], acc[m][n + 3]);
                *(float4*)&C[(size_t)r * M + col0 + tx * TN + n] = v;
            }
        }
    }
}

// ======= layer-3 special: h = z2 @ W3 (K=32, M=256) fused with attn coeffs ======
// warp per node (4 nodes per warp, strided); W3 + as3/ad3 staged in smem.
__global__ void __launch_bounds__(256)
gemm32_attn_kernel(const float* __restrict__ z2, const float* __restrict__ W3,
                   const float* __restrict__ as3, const float* __restrict__ ad3,
                   float* __restrict__ h, float* __restrict__ als,
                   float* __restrict__ ald) {
    __shared__ float W3s[32 * 256];
    __shared__ float as3s[256];
    __shared__ float ad3s[256];
    int tid = threadIdx.x;
    // stage W3 (8192 floats = 2048 float4)
#pragma unroll
    for (int p = 0; p < 8; p++)
        ((float4*)W3s)[tid + p * 256] = ((const float4*)W3)[tid + p * 256];
    if (tid < 64) ((float4*)as3s)[tid] = ((const float4*)as3)[tid];
    else if (tid < 128) ((float4*)ad3s)[tid - 64] = ((const float4*)ad3)[tid - 64];
    __syncthreads();

    int wid = tid >> 5, lane = tid & 31;
    int hd = lane >> 2;            // head owned by this lane's m-range
    const float4* W3s4 = (const float4*)W3s;
    const float4* as4 = (const float4*)as3s;
    const float4* ad4 = (const float4*)ad3s;

#pragma unroll
    for (int t = 0; t < 4; t++) {
        int node = blockIdx.x * 32 + wid + t * 8;
        if (node >= NN) return;
        float z = z2[(size_t)node * 32 + lane];
        float4 a0 = make_float4(0, 0, 0, 0), a1 = make_float4(0, 0, 0, 0);
#pragma unroll
        for (int k = 0; k < 32; k++) {
            float zk = __shfl_sync(0xffffffffu, z, k);
            float4 w0 = W3s4[k * 64 + lane * 2];
            float4 w1 = W3s4[k * 64 + lane * 2 + 1];
            a0.x += zk * w0.x; a0.y += zk * w0.y; a0.z += zk * w0.z; a0.w += zk * w0.w;
            a1.x += zk * w1.x; a1.y += zk * w1.y; a1.z += zk * w1.z; a1.w += zk * w1.w;
        }
        float4* hp = (float4*)(h + (size_t)node * 256);
        hp[lane * 2] = a0;
        hp[lane * 2 + 1] = a1;
        // attn coefficients: lane's 8 outputs all lie in head hd = lane>>2
        float4 s0 = as4[hd * 8 + (lane & 3) * 2], s1 = as4[hd * 8 + (lane & 3) * 2 + 1];
        float4 d0 = ad4[hd * 8 + (lane & 3) * 2], d1 = ad4[hd * 8 + (lane & 3) * 2 + 1];
        float s = a0.x * s0.x + a0.y * s0.y + a0.z * s0.z + a0.w * s0.w
                + a1.x * s1.x + a1.y * s1.y + a1.z * s1.z + a1.w * s1.w;
        float d = a0.x * d0.x + a0.y * d0.y + a0.z * d0.z + a0.w * d0.w
                + a1.x * d1.x + a1.y * d1.y + a1.z * d1.z + a1.w * d1.w;
        s += __shfl_xor_sync(0xffffffffu, s, 1);
        s += __shfl_xor_sync(0xffffffffu, s, 2);
        d += __shfl_xor_sync(0xffffffffu, d, 1);
        d += __shfl_xor_sync(0xffffffffu, d, 2);
        if ((lane & 3) == 0) {
            als[(size_t)node * 8 + hd] = s;
            ald[(size_t)node * 8 + hd] = d;
        }
    }
}

// ================= attention coefficients: als/ald [N,H] =================
template <int H, int C>
__global__ void attn_kernel(const float* __restrict__ h,
                            const float* __restrict__ asr,
                            const float* __restrict__ adr,
                            float* __restrict__ als, float* __restrict__ ald) {
    int idx = blockIdx.x * blockDim.x + threadIdx.x;  // = n*H + head
    if (idx >= NN * H) return;
    int hd = idx % H;
    const float4* hv = (const float4*)(h + (size_t)idx * C);
    const float4* av = (const float4*)(asr + hd * C);
    const float4* dv = (const float4*)(adr + hd * C);
    float s = 0.f, d = 0.f;
#pragma unroll
    for (int i = 0; i < C / 4; i++) {
        float4 x = hv[i], a = av[i], b = dv[i];
        s += x.x * a.x + x.y * a.y + x.z * a.z + x.w * a.w;
        d += x.x * b.x + x.y * b.y + x.z * b.z + x.w * b.w;
    }
    als[idx] = s;
    ald[idx] = d;
}

// ================= CSR aggregation (softmax-normalized), fused bias/relu =======
template <bool RELU>
__global__ void __launch_bounds__(256)
agg8_kernel(const int* __restrict__ off, const int* __restrict__ csr,
            const float* __restrict__ h, const float* __restrict__ als,
            const float* __restrict__ ald, const float* __restrict__ b,
            float* __restrict__ out) {
    int node = blockIdx.x * 8 + (threadIdx.x >> 5);
    if (node >= NN) return;
    int lane = threadIdx.x & 31;
    int hl = lane >> 3, hh = hl + 4;
    float aldl = ald[node * 8 + hl], aldh = ald[node * 8 + hh];
    float4 accl = make_float4(0, 0, 0, 0), acch = make_float4(0, 0, 0, 0);
    float wsl = 0.f, wsh = 0.f;
    int s0 = off[node], s1 = off[node + 1];
    for (int i = s0; i < s1; i++) {
        int src = __ldg(&csr[i]);
        const float4* hs = (const float4*)(h + (size_t)src * 256);
        float el = __ldg(&als[src * 8 + hl]) + aldl;
        float eh = __ldg(&als[src * 8 + hh]) + aldh;
        el = el > 0.f ? el : NEG_SLOPE * el;
        eh = eh > 0.f ? eh : NEG_SLOPE * eh;
        float wl = __expf(el), wh = __expf(eh);
        float4 h1 = hs[lane], h2 = hs[lane + 32];
        accl.x += wl * h1.x; accl.y += wl * h1.y; accl.z += wl * h1.z; accl.w += wl * h1.w;
        acch.x += wh * h2.x; acch.y += wh * h2.y; acch.z += wh * h2.z; acch.w += wh * h2.w;
        wsl += wl; wsh += wh;
    }
    float invl = 1.f / wsl, invh = 1.f / wsh;
    float4 b1 = ((const float4*)b)[lane], b2 = ((const float4*)b)[lane + 32];
    float4 o1 = make_float4(accl.x * invl + b1.x, accl.y * invl + b1.y,
                            accl.z * invl + b1.z, accl.w * invl + b1.w);
    float4 o2 = make_float4(acch.x * invh + b2.x, acch.y * invh + b2.y,
                            acch.z * invh + b2.z, acch.w * invh + b2.w);
    if (RELU) {
        o1.x = fmaxf(o1.x, 0.f); o1.y = fmaxf(o1.y, 0.f);
        o1.z = fmaxf(o1.z, 0.f); o1.w = fmaxf(o1.w, 0.f);
        o2.x = fmaxf(o2.x, 0.f); o2.y = fmaxf(o2.y, 0.f);
        o2.z = fmaxf(o2.z, 0.f); o2.w = fmaxf(o2.w, 0.f);
    }
    float4* op = (float4*)(out + (size_t)node * 256);
    op[lane] = o1;
    op[lane + 32] = o2;
}

__global__ void __launch_bounds__(256)
agg1c32_kernel(const int* __restrict__ off, const int* __restrict__ csr,
               const float* __restrict__ h, const float* __restrict__ als,
               const float* __restrict__ ald, const float* __restrict__ b,
               float* __restrict__ out) {
    int node = blockIdx.x * 8 + (threadIdx.x >> 5);
    if (node >= NN) return;
    int lane = threadIdx.x & 31, sub = lane >> 3, col = lane & 7;
    float aldn = ald[node];
    float4 acc = make_float4(0, 0, 0, 0);
    float ws = 0.f;
    int s0 = off[node], s1 = off[node + 1];
    for (int i = s0 + sub; i < s1; i += 4) {
        int src = __ldg(&csr[i]);
        float e = __ldg(&als[src]) + aldn;
        e = e > 0.f ? e : NEG_SLOPE * e;
        float w = __expf(e);
        float4 hv = ((const float4*)(h + (size_t)src * 32))[col];
        acc.x += w * hv.x; acc.y += w * hv.y; acc.z += w * hv.z; acc.w += w * hv.w;
        ws += w;
    }
#pragma unroll
    for (int m = 8; m <= 16; m <<= 1) {
        acc.x += __shfl_xor_sync(0xffffffffu, acc.x, m);
        acc.y += __shfl_xor_sync(0xffffffffu, acc.y, m);
        acc.z += __shfl_xor_sync(0xffffffffu, acc.z, m);
        acc.w += __shfl_xor_sync(0xffffffffu, acc.w, m);
        ws    += __shfl_xor_sync(0xffffffffu, ws, m);
    }
    if (sub == 0) {
        float inv = 1.f / ws;
        float4 bb = ((const float4*)b)[col];
        float4 o = make_float4(acc.x * inv + bb.x, acc.y * inv + bb.y,
                               acc.z * inv + bb.z, acc.w * inv + bb.w);
        ((float4*)(out + (size_t)node * 32))[col] = o;
    }
}

__global__ void __launch_bounds__(256)
agg1c128_kernel(const int* __restrict__ off, const int* __restrict__ csr,
                const float* __restrict__ h, const float* __restrict__ als,
                const float* __restrict__ ald, const float* __restrict__ b,
                float* __restrict__ out) {
    int node = blockIdx.x * 8 + (threadIdx.x >> 5);
    if (node >= NN) return;
    int lane = threadIdx.x & 31;
    float aldn = ald[node];
    float4 acc = make_float4(0, 0, 0, 0);
    float ws = 0.f;
    int s0 = off[node], s1 = off[node + 1];
    for (int i = s0; i < s1; i++) {
        int src = __ldg(&csr[i]);
        float e = __ldg(&als[src]) + aldn;
        e = e > 0.f ? e : NEG_SLOPE * e;
        float w = __expf(e);
        float4 hv = ((const float4*)(h + (size_t)src * 128))[lane];
        acc.x += w * hv.x; acc.y += w * hv.y; acc.z += w * hv.z; acc.w += w * hv.w;
        ws += w;
    }
    float inv = 1.f / ws;
    float4 bb = ((const float4*)b)[lane];
    float4 o = make_float4(acc.x * inv + bb.x, acc.y * inv + bb.y,
                           acc.z * inv + bb.z, acc.w * inv + bb.w);
    ((float4*)(out + (size_t)node * 128))[lane] = o;
}

// ================= launch =================
static inline int ceil_div_i(long long a, long long b) { return (int)((a + b - 1) / b); }

extern "C" void kernel_launch(void* const* d_in, const int* in_sizes, int n_in,
                              void* d_out, int out_size) {
    const float* x = (const float*)d_in[0];
    const int* ei = (const int*)d_in[1];   // int32 (JAX x64 disabled)
    const float* W1 = (const float*)d_in[2];
    const float* as1 = (const float*)d_in[3];
    const float* ad1 = (const float*)d_in[4];
    const float* b1 = (const float*)d_in[5];
    const float* W2 = (const float*)d_in[6];
    const float* as2 = (const float*)d_in[7];
    const float* ad2 = (const float*)d_in[8];
    const float* b2 = (const float*)d_in[9];
    const float* W3 = (const float*)d_in[10];
    const float* as3 = (const float*)d_in[11];
    const float* ad3 = (const float*)d_in[12];
    const float* b3 = (const float*)d_in[13];
    const float* W4 = (const float*)d_in[14];
    const float* as4 = (const float*)d_in[15];
    const float* ad4 = (const float*)d_in[16];
    const float* b4 = (const float*)d_in[17];
    float* out = (float*)d_out;

    float *h, *z1, *z2, *r1, *als, *ald;
    int *deg, *cnt, *off, *csr;
    cudaGetSymbolAddress((void**)&h, g_h);
    cudaGetSymbolAddress((void**)&z1, g_z1);
    cudaGetSymbolAddress((void**)&z2, g_z2);
    cudaGetSymbolAddress((void**)&r1, g_r1);
    cudaGetSymbolAddress((void**)&als, g_als);
    cudaGetSymbolAddress((void**)&ald, g_ald);
    cudaGetSymbolAddress((void**)&deg, g_deg);
    cudaGetSymbolAddress((void**)&cnt, g_cnt);
    cudaGetSymbolAddress((void**)&off, g_off);
    cudaGetSymbolAddress((void**)&csr, g_csr);

    const int TPB = 256;
    const int rowBlocks = ceil_div_i(NN, 128);
    const int aggBlocks = ceil_div_i(NN, 8);

    // ---- CSR build (by dst), reused by all 4 layers ----
    cudaMemsetAsync(deg, 0, NN * sizeof(int), 0);
    cudaMemsetAsync(cnt, 0, NN * sizeof(int), 0);
    hist_kernel<<<ceil_div_i(NE, TPB), TPB>>>(ei, deg);
    scan_kernel<<<1, 1024>>>(deg, off);
    scatter_kernel<<<ceil_div_i(NE + NN, TPB), TPB>>>(ei, off, cnt, csr);

    // ===== Layer 1: 128 -> [8 x 32], relu =====
    sgemm_db_kernel<128, 128, 16, 8, 8><<<dim3(rowBlocks, 2), 256>>>(NN, 128, 256, x, W1, h);
    attn_kernel<8, 32><<<ceil_div_i((long long)NN * 8, TPB), TPB>>>(h, as1, ad1, als, ald);
    agg8_kernel<true><<<aggBlocks, TPB>>>(off, csr, h, als, ald, b1, z1);

    // ===== Layer 2: 256 -> 32 =====
    sgemm_db_kernel<128, 32, 16, 8, 4><<<dim3(rowBlocks, 1), 128>>>(NN, 256, 32, z1, W2, h);
    attn_kernel<1, 32><<<ceil_div_i(NN, TPB), TPB>>>(h, as2, ad2, als, ald);
    agg1c32_kernel<<<aggBlocks, TPB>>>(off, csr, h, als, ald, b2, z2);

    // ===== Layer 3: 32 -> [8 x 32], relu (special small-K kernel, fused attn) =====
    gemm32_attn_kernel<<<ceil_div_i(NN, 32), 256>>>(z2, W3, as3, ad3, h, als, ald);
    agg8_kernel<true><<<aggBlocks, TPB>>>(off, csr, h, als, ald, b3, r1);

    // ===== Layer 4: 256 -> 128 =====
    sgemm_db_kernel<128, 128, 16, 8, 8><<<dim3(rowBlocks, 1), 256>>>(NN, 256, 128, r1, W4, h);
    attn_kernel<1, 128><<<ceil_div_i(NN, TPB), TPB>>>(h, as4, ad4, als, ald);
    agg1c128_kernel<<<aggBlocks, TPB>>>(off, csr, h, als, ald, b4, out);
}